// round 10
// baseline (speedup 1.0000x reference)
#include <cuda_runtime.h>

// Temporal cosine regularizer, single fused kernel (R10 = R9 bytes + R8 warps).
//   out = -0.02/(N-1) * sum_i <x_i,x_{i+1}> / (max(||x_i||,eps)*max(||x_{i+1}||,eps))
//
// HBM-bound, 512 MiB read-once. R9 (RPB=128, 256 thr) halved boundary bytes but
// grid 512 underfilled SMs (28 warps/SM, occ 41%, BW -2%). R10 keeps RPB=128
// and doubles the block to 512 threads: 512 blocks x 16 warps / 148 SMs
// ~= 55 warps/SM (same as the R8 champion). One float4 per thread per row
// (COLS/4 == NTHREADS), __ldcg L2-direct stream, no per-row __syncthreads,
// fused deterministic last-block finalize.

#define COLS     2048
#define RPB      128
#define NTHREADS 512
#define NWARPS   (NTHREADS / 32)   // 16

__device__ float        g_partials[8192];
__device__ unsigned int g_count = 0;

__device__ __forceinline__ float warp_reduce_f(float v) {
#pragma unroll
    for (int o = 16; o > 0; o >>= 1) v += __shfl_xor_sync(0xffffffffu, v, o);
    return v;
}

__global__ void __launch_bounds__(NTHREADS)
pair_dot_fused_kernel(const float* __restrict__ x, int N, float* __restrict__ out) {
    __shared__ float s_sq[RPB + 1][NWARPS];   // 8.25 KB
    __shared__ float s_dp[RPB + 1][NWARPS];   // 8.25 KB
    __shared__ bool  s_last;

    const int tid  = threadIdx.x;
    const int lane = tid & 31;
    const int warp = tid >> 5;
    const int r0   = blockIdx.x * RPB;

    // Row r0: norm^2 only; becomes "prev". One float4 per thread.
    float prev[4];
    {
        const float4* rp = reinterpret_cast<const float4*>(x + (size_t)r0 * COLS);
        float4 a = __ldcg(rp + tid);
        prev[0] = a.x; prev[1] = a.y; prev[2] = a.z; prev[3] = a.w;
        float sq = 0.0f;
#pragma unroll
        for (int j = 0; j < 4; ++j) sq = fmaf(prev[j], prev[j], sq);
        sq = warp_reduce_f(sq);
        if (lane == 0) s_sq[0][warp] = sq;
    }

    // Rows r0+1 .. r0+RPB: norm^2 and dot with previous row.
#pragma unroll 4
    for (int rr = 1; rr <= RPB; ++rr) {
        const int r = r0 + rr;
        float sq = 0.0f, dp = 0.0f;
        if (r < N) {
            const float4* rp = reinterpret_cast<const float4*>(x + (size_t)r * COLS);
            float4 a = __ldcg(rp + tid);
            float cur[4] = {a.x, a.y, a.z, a.w};
#pragma unroll
            for (int j = 0; j < 4; ++j) {
                sq = fmaf(cur[j], cur[j], sq);
                dp = fmaf(cur[j], prev[j], dp);
                prev[j] = cur[j];
            }
        }
        sq = warp_reduce_f(sq);
        dp = warp_reduce_f(dp);
        if (lane == 0) { s_sq[rr][warp] = sq; s_dp[rr][warp] = dp; }
    }
    __syncthreads();

    // Warp 0: combine NWARPS warp-partials per row, cosine terms, fp64 accumulate.
    if (warp == 0) {
        double acc = 0.0;
        for (int rr = 1 + lane; rr <= RPB; rr += 32) {
            if (r0 + rr < N) {  // dot index r0+rr-1 must be <= N-2
                float n2a = 0.0f, n2b = 0.0f, d8 = 0.0f;
#pragma unroll
                for (int w = 0; w < NWARPS; ++w) {
                    n2a += s_sq[rr - 1][w];
                    n2b += s_sq[rr][w];
                    d8  += s_dp[rr][w];
                }
                float na = fmaxf(sqrtf(n2a), 1e-12f);
                float nb = fmaxf(sqrtf(n2b), 1e-12f);
                acc += (double)(d8 / (na * nb));
            }
        }
#pragma unroll
        for (int o = 16; o > 0; o >>= 1)
            acc += __shfl_xor_sync(0xffffffffu, acc, o);
        if (lane == 0) g_partials[blockIdx.x] = (float)acc;
    }

    // ---- last-block-done: deterministic final reduction ----
    __threadfence();
    if (tid == 0) {
        unsigned int prev_cnt = atomicAdd(&g_count, 1u);
        s_last = (prev_cnt == gridDim.x - 1);
    }
    __syncthreads();

    if (s_last) {
        __shared__ double sd[NTHREADS];
        const int nb = gridDim.x;
        double a = 0.0;
        for (int i = tid; i < nb; i += NTHREADS)
            a += (double)__ldcg(&g_partials[i]);
        sd[tid] = a;
        __syncthreads();
#pragma unroll
        for (int o = NTHREADS / 2; o > 0; o >>= 1) {
            if (tid < o) sd[tid] += sd[tid + o];
            __syncthreads();
        }
        if (tid == 0) {
            out[0] = (float)(-2.0 * 0.01 * sd[0] / (double)(N - 1));
            g_count = 0;  // reset for next graph replay
        }
    }
}

extern "C" void kernel_launch(void* const* d_in, const int* in_sizes, int n_in,
                              void* d_out, int out_size) {
    const float* x = (const float*)d_in[0];
    const int N = in_sizes[0] / COLS;            // 65536
    const int nblocks = (N - 1 + RPB - 1) / RPB; // 512
    pair_dot_fused_kernel<<<nblocks, NTHREADS>>>(x, N, (float*)d_out);
}

// round 11
// speedup vs baseline: 1.0784x; 1.0784x over previous
#include <cuda_runtime.h>

// Temporal cosine regularizer, single fused kernel (R11 = R8 + serpentine).
//   out = -0.02/(N-1) * sum_i <x_i,x_{i+1}> / (max(||x_i||,eps)*max(||x_{i+1}||,eps))
//
// HBM-bound, 512 MiB read-once. R8 shape is the measured best (256 thr,
// 8 elems/thread, RPB=64, __ldcg, 6309 GB/s). R11 adds serpentine row order:
// odd blocks stream their rows BACKWARD, so each boundary row shared with a
// neighbor is touched by both at nearly the same time (start-start / end-end
// within the single resident wave) -> second access is an L2 hit instead of a
// DRAM re-read (saves the 1.56% overlap, ~8 MB).
// Storage normalized: s_sq[i] = ||row r0+i||^2, s_dp[j] = <row r0+j, row r0+j+1>.

#define COLS     2048
#define RPB      64
#define NTHREADS 256

__device__ float        g_partials[8192];
__device__ unsigned int g_count = 0;

__device__ __forceinline__ float warp_reduce_f(float v) {
#pragma unroll
    for (int o = 16; o > 0; o >>= 1) v += __shfl_xor_sync(0xffffffffu, v, o);
    return v;
}

__global__ void __launch_bounds__(NTHREADS)
pair_dot_fused_kernel(const float* __restrict__ x, int N, float* __restrict__ out) {
    __shared__ float s_sq[RPB + 1][8];
    __shared__ float s_dp[RPB][8];
    __shared__ bool  s_last;

    const int tid  = threadIdx.x;
    const int lane = tid & 31;
    const int warp = tid >> 5;
    const int r0   = blockIdx.x * RPB;
    const bool fwd = (blockIdx.x & 1) == 0;   // serpentine direction

    // First streamed local row index: 0 (fwd) or RPB (bwd).
    float prev[8];
    {
        const int i0 = fwd ? 0 : RPB;
        const int r  = r0 + i0;
        float sq = 0.0f;
        if (r < N) {
            const float4* rp = reinterpret_cast<const float4*>(x + (size_t)r * COLS);
            float4 a = __ldcg(rp + tid);
            float4 b = __ldcg(rp + tid + NTHREADS);
            prev[0]=a.x; prev[1]=a.y; prev[2]=a.z; prev[3]=a.w;
            prev[4]=b.x; prev[5]=b.y; prev[6]=b.z; prev[7]=b.w;
#pragma unroll
            for (int j = 0; j < 8; ++j) sq = fmaf(prev[j], prev[j], sq);
        } else {
#pragma unroll
            for (int j = 0; j < 8; ++j) prev[j] = 0.0f;
        }
        sq = warp_reduce_f(sq);
        if (lane == 0) s_sq[i0][warp] = sq;
    }

    // Remaining RPB rows. fwd: i = k (rows 1..RPB), dot slot i-1.
    //                     bwd: i = RPB-k (rows RPB-1..0), dot slot i.
#pragma unroll 4
    for (int k = 1; k <= RPB; ++k) {
        const int i = fwd ? k : (RPB - k);
        const int r = r0 + i;
        float sq = 0.0f, dp = 0.0f;
        if (r < N) {
            const float4* rp = reinterpret_cast<const float4*>(x + (size_t)r * COLS);
            float4 a = __ldcg(rp + tid);
            float4 b = __ldcg(rp + tid + NTHREADS);
            float cur[8] = {a.x, a.y, a.z, a.w, b.x, b.y, b.z, b.w};
#pragma unroll
            for (int j = 0; j < 8; ++j) {
                sq = fmaf(cur[j], cur[j], sq);
                dp = fmaf(cur[j], prev[j], dp);
                prev[j] = cur[j];
            }
        }
        sq = warp_reduce_f(sq);
        dp = warp_reduce_f(dp);
        if (lane == 0) {
            s_sq[i][warp] = sq;
            s_dp[fwd ? (i - 1) : i][warp] = dp;  // dot(r0+slot, r0+slot+1)
        }
    }
    __syncthreads();

    // Warp 0: cosine terms for dot slots j = 0..RPB-1 (dot index r0+j),
    // valid when r0+j+1 < N. fp64 accumulate, fixed order.
    if (warp == 0) {
        double acc = 0.0;
        for (int j = lane; j < RPB; j += 32) {
            if (r0 + j + 1 < N) {
                float n2a = 0.0f, n2b = 0.0f, d8 = 0.0f;
#pragma unroll
                for (int w = 0; w < 8; ++w) {
                    n2a += s_sq[j][w];
                    n2b += s_sq[j + 1][w];
                    d8  += s_dp[j][w];
                }
                float na = fmaxf(sqrtf(n2a), 1e-12f);
                float nb = fmaxf(sqrtf(n2b), 1e-12f);
                acc += (double)(d8 / (na * nb));
            }
        }
#pragma unroll
        for (int o = 16; o > 0; o >>= 1)
            acc += __shfl_xor_sync(0xffffffffu, acc, o);
        if (lane == 0) g_partials[blockIdx.x] = (float)acc;
    }

    // ---- last-block-done: deterministic final reduction ----
    __threadfence();
    if (tid == 0) {
        unsigned int prev_cnt = atomicAdd(&g_count, 1u);
        s_last = (prev_cnt == gridDim.x - 1);
    }
    __syncthreads();

    if (s_last) {
        __shared__ double sd[NTHREADS];
        const int nb = gridDim.x;
        double a = 0.0;
        for (int i = tid; i < nb; i += NTHREADS)
            a += (double)__ldcg(&g_partials[i]);
        sd[tid] = a;
        __syncthreads();
#pragma unroll
        for (int o = NTHREADS / 2; o > 0; o >>= 1) {
            if (tid < o) sd[tid] += sd[tid + o];
            __syncthreads();
        }
        if (tid == 0) {
            out[0] = (float)(-2.0 * 0.01 * sd[0] / (double)(N - 1));
            g_count = 0;  // reset for next graph replay
        }
    }
}

extern "C" void kernel_launch(void* const* d_in, const int* in_sizes, int n_in,
                              void* d_out, int out_size) {
    const float* x = (const float*)d_in[0];
    const int N = in_sizes[0] / COLS;            // 65536
    const int nblocks = (N - 1 + RPB - 1) / RPB; // 1024
    pair_dot_fused_kernel<<<nblocks, NTHREADS>>>(x, N, (float*)d_out);
}